// round 6
// baseline (speedup 1.0000x reference)
#include <cuda_runtime.h>
#include <cuda_bf16.h>
#include <math.h>

// Problem constants (from reference setup_inputs)
constexpr int D      = 128;    // feature dim
constexpr int KNBR   = 32;     // neighbors per node
constexpr int MAXN   = 50000;  // nodes
constexpr int BM     = 64;     // GEMM row tile
constexpr int BK     = 32;     // GEMM k tile

// Scratch (static device globals — no cudaMalloc allowed)
__device__ float g_msg[(size_t)MAXN * D];
__device__ float g_x  [(size_t)MAXN * D];

// ---------------------------------------------------------------------------
// Tiled fp32 GEMM: out[N,D] = (X[N,D] (*mask?)) @ W[D,D], output *= mask.
// 256 threads, BM=64 rows per block, full D=128 cols, K tiled by 32.
// Each thread: 8 rows x 4 cols register block.
// ---------------------------------------------------------------------------
template<bool MASK_IN>
__global__ __launch_bounds__(256) void gemm_kernel(
    const float* __restrict__ X, const float* __restrict__ W,
    const float* __restrict__ mask, float* __restrict__ out, int N)
{
    __shared__ float Xs[BM][BK];     // [row][k] — warp reads same addr (broadcast)
    __shared__ float Ws[BK][D];      // [k][col] — float4 reads, conflict-free

    const int tid = threadIdx.x;
    const int m0  = blockIdx.x * BM;
    const int tm  = (tid >> 5) * 8;      // row group base within tile
    const int tc  = (tid & 31) * 4;      // col base

    float acc[8][4] = {};

    for (int kt = 0; kt < D; kt += BK) {
        // Load X tile (64x32): 8 floats/thread, coalesced 128B per row-chunk
        #pragma unroll
        for (int i = 0; i < (BM * BK) / 256; i++) {
            int li  = tid + i * 256;
            int m   = li >> 5;
            int k   = li & 31;
            int row = m0 + m;
            float v = 0.0f;
            if (row < N) {
                v = X[(size_t)row * D + kt + k];
                if (MASK_IN) v *= mask[row];
            }
            Xs[m][k] = v;
        }
        // Load W tile (32x128): 16 floats/thread
        #pragma unroll
        for (int i = 0; i < (BK * D) / 256; i++) {
            int li = tid + i * 256;
            int k  = li >> 7;
            int c  = li & 127;
            Ws[k][c] = W[(size_t)(kt + k) * D + c];
        }
        __syncthreads();

        #pragma unroll
        for (int k = 0; k < BK; k++) {
            float4 wv = *reinterpret_cast<const float4*>(&Ws[k][tc]);
            #pragma unroll
            for (int i = 0; i < 8; i++) {
                float xv = Xs[tm + i][k];
                acc[i][0] = fmaf(xv, wv.x, acc[i][0]);
                acc[i][1] = fmaf(xv, wv.y, acc[i][1]);
                acc[i][2] = fmaf(xv, wv.z, acc[i][2]);
                acc[i][3] = fmaf(xv, wv.w, acc[i][3]);
            }
        }
        __syncthreads();
    }

    #pragma unroll
    for (int i = 0; i < 8; i++) {
        int row = m0 + tm + i;
        if (row < N) {
            float mk = mask[row];
            float4 o = make_float4(acc[i][0] * mk, acc[i][1] * mk,
                                   acc[i][2] * mk, acc[i][3] * mk);
            *reinterpret_cast<float4*>(&out[(size_t)row * D + tc]) = o;
        }
    }
}

// ---------------------------------------------------------------------------
// Gather + weighted sum + exp_map_zero + relu (+ optional fused log_map for
// the next layer). One warp per node; lane l owns float4 = dims [4l, 4l+4).
// adj/weight rows (K=32) loaded one-per-lane, broadcast via shfl.
// ---------------------------------------------------------------------------
template<bool FUSE_LOGMAP>
__global__ __launch_bounds__(256) void gather_kernel(
    const float* __restrict__ msg, const int* __restrict__ adj,
    const float* __restrict__ wgt, const float* __restrict__ mask,
    float* __restrict__ out, int N)
{
    const int warp = (blockIdx.x * blockDim.x + threadIdx.x) >> 5;
    const int lane = threadIdx.x & 31;
    if (warp >= N) return;
    const int n = warp;

    // Each lane holds one (neighbor, weight) pair; K == warpSize == 32
    const int   a_reg = adj[(size_t)n * KNBR + lane];
    const float w_reg = wgt[(size_t)n * KNBR + lane];

    const float4* msg4 = reinterpret_cast<const float4*>(msg);
    float4 acc = make_float4(0.f, 0.f, 0.f, 0.f);

    #pragma unroll
    for (int k = 0; k < KNBR; k++) {
        int   ak = __shfl_sync(0xffffffffu, a_reg, k);
        float wk = __shfl_sync(0xffffffffu, w_reg, k);
        float4 v = msg4[(size_t)ak * (D / 4) + lane];
        acc.x = fmaf(wk, v.x, acc.x);
        acc.y = fmaf(wk, v.y, acc.y);
        acc.z = fmaf(wk, v.z, acc.z);
        acc.w = fmaf(wk, v.w, acc.w);
    }

    const float mk = mask[n];
    // combined = einsum * mask
    acc.x *= mk; acc.y *= mk; acc.z *= mk; acc.w *= mk;

    // exp_map_zero: tanh(clip(||v||, EPS, 15)) * v / max(||v||, EPS)
    float ss = acc.x * acc.x + acc.y * acc.y + acc.z * acc.z + acc.w * acc.w;
    #pragma unroll
    for (int o = 16; o; o >>= 1) ss += __shfl_xor_sync(0xffffffffu, ss, o);
    float nn = sqrtf(ss);
    float nc = fminf(fmaxf(nn, 1e-5f), 15.0f);
    float sc = (tanhf(nc) / fmaxf(nn, 1e-5f)) * mk;   // exp map scale * mask

    // x = relu(expmap * mask) * mask
    float4 x;
    x.x = fmaxf(acc.x * sc, 0.0f) * mk;
    x.y = fmaxf(acc.y * sc, 0.0f) * mk;
    x.z = fmaxf(acc.z * sc, 0.0f) * mk;
    x.w = fmaxf(acc.w * sc, 0.0f) * mk;

    if (FUSE_LOGMAP) {
        // next layer prologue: t = log_map_zero(x) * mask
        float s2 = x.x * x.x + x.y * x.y + x.z * x.z + x.w * x.w;
        #pragma unroll
        for (int o = 16; o; o >>= 1) s2 += __shfl_xor_sync(0xffffffffu, s2, o);
        float n2  = sqrtf(s2);
        float n2c = fminf(fmaxf(n2, 1e-5f), 1.0f - 1e-5f);
        float sl  = (atanhf(n2c) / fmaxf(n2, 1e-5f)) * mk;
        x.x *= sl; x.y *= sl; x.z *= sl; x.w *= sl;
    }

    reinterpret_cast<float4*>(out)[(size_t)n * (D / 4) + lane] = x;
}

// ---------------------------------------------------------------------------
// Launch: 2 layers x (GEMM, gather). All on the capture stream (default).
// ---------------------------------------------------------------------------
extern "C" void kernel_launch(void* const* d_in, const int* in_sizes, int n_in,
                              void* d_out, int out_size)
{
    const float* node_repr = (const float*)d_in[0];   // [N, D]
    const int*   adj_mat   = (const int*)  d_in[1];   // [N, K]
    const float* weight    = (const float*)d_in[2];   // [N, K]
    const float* mask      = (const float*)d_in[3];   // [N, 1]
    const float* msg_w     = (const float*)d_in[4];   // [2, D, D]
    float*       out       = (float*)d_out;           // [N, D]

    const int N = in_sizes[0] / D;

    float *msg_buf, *x_buf;
    cudaGetSymbolAddress((void**)&msg_buf, g_msg);
    cudaGetSymbolAddress((void**)&x_buf,   g_x);

    dim3 gemm_grid((N + BM - 1) / BM);
    int  gather_blocks = (N * 32 + 255) / 256;        // 1 warp per node

    // Layer 0: x = node_repr * mask (MASK_IN); msg = (x@W0)*mask
    gemm_kernel<true><<<gemm_grid, 256>>>(node_repr, msg_w, mask, msg_buf, N);
    // gather + expmap + relu, fused logmap for layer 1 -> x_buf (tangent space)
    gather_kernel<true><<<gather_blocks, 256>>>(msg_buf, adj_mat, weight, mask, x_buf, N);

    // Layer 1: x_buf already = logmap(x)*mask; msg = (x@W1)*mask
    gemm_kernel<false><<<gemm_grid, 256>>>(x_buf, msg_w + D * D, mask, msg_buf, N);
    // final gather + expmap + relu -> d_out
    gather_kernel<false><<<gather_blocks, 256>>>(msg_buf, adj_mat, weight, mask, out, N);
}

// round 7
// speedup vs baseline: 1.1045x; 1.1045x over previous
#include <cuda_runtime.h>
#include <cuda_bf16.h>
#include <math.h>
#include <stdint.h>

// Problem constants (from reference setup_inputs)
constexpr int D      = 128;    // feature dim
constexpr int KNBR   = 32;     // neighbors per node
constexpr int MAXN   = 50000;  // nodes

// Scratch (static device globals — no cudaMalloc allowed)
__device__ float g_msg[(size_t)MAXN * D];
__device__ float g_x  [(size_t)MAXN * D];

__device__ __forceinline__ uint32_t f2tf32(float f) {
    uint32_t u;
    asm("cvt.rna.tf32.f32 %0, %1;" : "=r"(u) : "f"(f));
    return u;
}

// ---------------------------------------------------------------------------
// tf32 tensor-core GEMM: out[N,D] = (X[N,D] (*mask?)) @ W[D,D], output *= mask.
// 256 threads / 8 warps, BM=128 rows per CTA, K chunked by 32.
// Warp w computes rows [16w, 16w+16) x all 128 cols via m16n8k8 tf32 MMA.
// Fragment layout (PTX m16n8k8.row.col):
//   A: a0=(gid, tig) a1=(gid+8, tig) a2=(gid, tig+4) a3=(gid+8, tig+4)
//   B: b0=(tig, gid) b1=(tig+4, gid)       [k x n, col layout]
//   C: c0=(gid, 2*tig) c1=(gid, 2*tig+1) c2=(gid+8, 2*tig) c3=(gid+8, 2*tig+1)
// Smem pads: Xs stride 36 -> A-frag bank = (4*gid+tig) all-distinct;
//            Ws stride 136 -> B-frag bank = (8*tig+gid) all-distinct.
// ---------------------------------------------------------------------------
template<bool MASK_IN>
__global__ __launch_bounds__(256) void gemm_tf32_kernel(
    const float* __restrict__ X, const float* __restrict__ W,
    const float* __restrict__ mask, float* __restrict__ out, int N)
{
    __shared__ uint32_t Xs[128][36];    // 128 x 32 tf32, pad 4
    __shared__ uint32_t Ws[32][136];    // 32 x 128 tf32, pad 8

    const int tid  = threadIdx.x;
    const int m0   = blockIdx.x * 128;
    const int warp = tid >> 5;
    const int lane = tid & 31;
    const int gid  = lane >> 2;          // 0..7
    const int tig  = lane & 3;           // 0..3

    float c[16][4];
    #pragma unroll
    for (int nt = 0; nt < 16; nt++) {
        c[nt][0] = 0.f; c[nt][1] = 0.f; c[nt][2] = 0.f; c[nt][3] = 0.f;
    }

    for (int kt = 0; kt < 4; kt++) {                 // K chunks of 32
        // Load X tile (128x32), convert to tf32, optional input mask
        #pragma unroll
        for (int i = 0; i < 16; i++) {
            int li  = tid + i * 256;
            int m   = li >> 5;
            int k   = li & 31;
            int row = m0 + m;
            float v = 0.0f;
            if (row < N) {
                v = X[(size_t)row * D + kt * 32 + k];
                if (MASK_IN) v *= mask[row];
            }
            Xs[m][k] = f2tf32(v);
        }
        // Load W tile (32x128), convert to tf32
        #pragma unroll
        for (int i = 0; i < 16; i++) {
            int li = tid + i * 256;
            int k  = li >> 7;
            int cc = li & 127;
            Ws[k][cc] = f2tf32(W[(size_t)(kt * 32 + k) * D + cc]);
        }
        __syncthreads();

        #pragma unroll
        for (int kk = 0; kk < 4; kk++) {             // k-tiles of 8
            const int k0 = kk * 8;
            const int ra = warp * 16 + gid;
            uint32_t a0 = Xs[ra    ][k0 + tig    ];
            uint32_t a1 = Xs[ra + 8][k0 + tig    ];
            uint32_t a2 = Xs[ra    ][k0 + tig + 4];
            uint32_t a3 = Xs[ra + 8][k0 + tig + 4];
            #pragma unroll
            for (int nt = 0; nt < 16; nt++) {
                uint32_t b0 = Ws[k0 + tig    ][nt * 8 + gid];
                uint32_t b1 = Ws[k0 + tig + 4][nt * 8 + gid];
                asm volatile(
                    "mma.sync.aligned.m16n8k8.row.col.f32.tf32.tf32.f32 "
                    "{%0,%1,%2,%3}, {%4,%5,%6,%7}, {%8,%9}, {%0,%1,%2,%3};\n"
                    : "+f"(c[nt][0]), "+f"(c[nt][1]),
                      "+f"(c[nt][2]), "+f"(c[nt][3])
                    : "r"(a0), "r"(a1), "r"(a2), "r"(a3),
                      "r"(b0), "r"(b1));
            }
        }
        __syncthreads();
    }

    // Epilogue: multiply by mask[row], store. Each group-of-4 lanes covers one
    // 32B sector per n-tile row -> full sector utilization.
    const int r0 = m0 + warp * 16 + gid;
    const int r1 = r0 + 8;
    const float mk0 = (r0 < N) ? mask[r0] : 0.f;
    const float mk1 = (r1 < N) ? mask[r1] : 0.f;
    #pragma unroll
    for (int nt = 0; nt < 16; nt++) {
        int col = nt * 8 + tig * 2;
        if (r0 < N) {
            float2 o = make_float2(c[nt][0] * mk0, c[nt][1] * mk0);
            *reinterpret_cast<float2*>(&out[(size_t)r0 * D + col]) = o;
        }
        if (r1 < N) {
            float2 o = make_float2(c[nt][2] * mk1, c[nt][3] * mk1);
            *reinterpret_cast<float2*>(&out[(size_t)r1 * D + col]) = o;
        }
    }
}

// ---------------------------------------------------------------------------
// Gather + weighted sum + exp_map_zero + relu (+ optional fused log_map for
// the next layer). One warp per node; lane l owns float4 = dims [4l, 4l+4).
// ---------------------------------------------------------------------------
template<bool FUSE_LOGMAP>
__global__ __launch_bounds__(256) void gather_kernel(
    const float* __restrict__ msg, const int* __restrict__ adj,
    const float* __restrict__ wgt, const float* __restrict__ mask,
    float* __restrict__ out, int N)
{
    const int warp = (blockIdx.x * blockDim.x + threadIdx.x) >> 5;
    const int lane = threadIdx.x & 31;
    if (warp >= N) return;
    const int n = warp;

    const int   a_reg = adj[(size_t)n * KNBR + lane];
    const float w_reg = wgt[(size_t)n * KNBR + lane];

    const float4* msg4 = reinterpret_cast<const float4*>(msg);
    float4 acc = make_float4(0.f, 0.f, 0.f, 0.f);

    #pragma unroll
    for (int k = 0; k < KNBR; k++) {
        int   ak = __shfl_sync(0xffffffffu, a_reg, k);
        float wk = __shfl_sync(0xffffffffu, w_reg, k);
        float4 v = msg4[(size_t)ak * (D / 4) + lane];
        acc.x = fmaf(wk, v.x, acc.x);
        acc.y = fmaf(wk, v.y, acc.y);
        acc.z = fmaf(wk, v.z, acc.z);
        acc.w = fmaf(wk, v.w, acc.w);
    }

    const float mk = mask[n];
    acc.x *= mk; acc.y *= mk; acc.z *= mk; acc.w *= mk;

    // exp_map_zero
    float ss = acc.x * acc.x + acc.y * acc.y + acc.z * acc.z + acc.w * acc.w;
    #pragma unroll
    for (int o = 16; o; o >>= 1) ss += __shfl_xor_sync(0xffffffffu, ss, o);
    float nn = sqrtf(ss);
    float nc = fminf(fmaxf(nn, 1e-5f), 15.0f);
    float sc = (tanhf(nc) / fmaxf(nn, 1e-5f)) * mk;

    float4 x;
    x.x = fmaxf(acc.x * sc, 0.0f) * mk;
    x.y = fmaxf(acc.y * sc, 0.0f) * mk;
    x.z = fmaxf(acc.z * sc, 0.0f) * mk;
    x.w = fmaxf(acc.w * sc, 0.0f) * mk;

    if (FUSE_LOGMAP) {
        float s2 = x.x * x.x + x.y * x.y + x.z * x.z + x.w * x.w;
        #pragma unroll
        for (int o = 16; o; o >>= 1) s2 += __shfl_xor_sync(0xffffffffu, s2, o);
        float n2  = sqrtf(s2);
        float n2c = fminf(fmaxf(n2, 1e-5f), 1.0f - 1e-5f);
        float sl  = (atanhf(n2c) / fmaxf(n2, 1e-5f)) * mk;
        x.x *= sl; x.y *= sl; x.z *= sl; x.w *= sl;
    }

    reinterpret_cast<float4*>(out)[(size_t)n * (D / 4) + lane] = x;
}

// ---------------------------------------------------------------------------
// Launch: 2 layers x (tf32 GEMM, gather).
// ---------------------------------------------------------------------------
extern "C" void kernel_launch(void* const* d_in, const int* in_sizes, int n_in,
                              void* d_out, int out_size)
{
    const float* node_repr = (const float*)d_in[0];   // [N, D]
    const int*   adj_mat   = (const int*)  d_in[1];   // [N, K]
    const float* weight    = (const float*)d_in[2];   // [N, K]
    const float* mask      = (const float*)d_in[3];   // [N, 1]
    const float* msg_w     = (const float*)d_in[4];   // [2, D, D]
    float*       out       = (float*)d_out;           // [N, D]

    const int N = in_sizes[0] / D;

    float *msg_buf, *x_buf;
    cudaGetSymbolAddress((void**)&msg_buf, g_msg);
    cudaGetSymbolAddress((void**)&x_buf,   g_x);

    dim3 gemm_grid((N + 127) / 128);
    int  gather_blocks = (N * 32 + 255) / 256;        // 1 warp per node

    // Layer 0
    gemm_tf32_kernel<true><<<gemm_grid, 256>>>(node_repr, msg_w, mask, msg_buf, N);
    gather_kernel<true><<<gather_blocks, 256>>>(msg_buf, adj_mat, weight, mask, x_buf, N);

    // Layer 1
    gemm_tf32_kernel<false><<<gemm_grid, 256>>>(x_buf, msg_w + D * D, mask, msg_buf, N);
    gather_kernel<false><<<gather_blocks, 256>>>(msg_buf, adj_mat, weight, mask, out, N);
}

// round 13
// speedup vs baseline: 1.7533x; 1.5875x over previous
#include <cuda_runtime.h>
#include <cuda_bf16.h>
#include <cuda_fp16.h>
#include <math.h>
#include <stdint.h>

// Problem constants (from reference setup_inputs)
constexpr int D      = 128;    // feature dim
constexpr int KNBR   = 32;     // neighbors per node
constexpr int MAXN   = 50000;  // nodes

// Scratch (static device globals — no cudaMalloc allowed)
__device__ __half g_msg[(size_t)MAXN * D];   // fp16 message table (12.8 MB)
__device__ float  g_x  [(size_t)MAXN * D];   // fp32 tangent-space features

__device__ __forceinline__ uint32_t f2tf32(float f) {
    uint32_t u;
    asm("cvt.rna.tf32.f32 %0, %1;" : "=r"(u) : "f"(f));
    return u;
}

// ---------------------------------------------------------------------------
// tf32 tensor-core GEMM: msg[N,D](fp16) = ((X[N,D] (*mask?)) @ W[D,D]) * mask.
// 256 threads / 8 warps, BM=128 rows per CTA, K chunked by 32, register
// prefetch double-buffering of the next k-chunk's global loads.
// Warp w computes rows [16w,16w+16) x all 128 cols via m16n8k8 tf32 MMA.
// Fragment layout (PTX m16n8k8.row.col):
//   A: a0=(gid, tig) a1=(gid+8, tig) a2=(gid, tig+4) a3=(gid+8, tig+4)
//   B: b0=(tig, gid) b1=(tig+4, gid)       [k x n, col layout]
//   C: c0=(gid, 2*tig) c1=(gid, 2*tig+1) c2=(gid+8, 2*tig) c3=(gid+8, 2*tig+1)
// Smem pads: Xs stride 36 -> A-frag bank = (4*gid+tig) all-distinct;
//            Ws stride 136 -> B-frag bank = (8*tig+gid) all-distinct.
// ---------------------------------------------------------------------------
template<bool MASK_IN>
__global__ __launch_bounds__(256) void gemm_tf32_kernel(
    const float* __restrict__ X, const float* __restrict__ W,
    const float* __restrict__ mask, __half* __restrict__ out, int N)
{
    __shared__ uint32_t Xs[128][36];    // 128 x 32 tf32, pad 4
    __shared__ uint32_t Ws[32][136];    // 32 x 128 tf32, pad 8

    const int tid  = threadIdx.x;
    const int m0   = blockIdx.x * 128;
    const int warp = tid >> 5;
    const int lane = tid & 31;
    const int gid  = lane >> 2;          // 0..7
    const int tig  = lane & 3;           // 0..3

    // Per-thread global-load coordinates (fixed across k-chunks)
    const int xm = tid >> 5;             // X tile row (thread covers rows xm, xm+8, ..)
    const int xk = tid & 31;             // X tile col within chunk
    const int wk = tid >> 7;             // W tile row (thread covers rows wk, wk+2, ..)
    const int wc = tid & 127;            // W tile col

    float c[16][4];
    #pragma unroll
    for (int nt = 0; nt < 16; nt++) {
        c[nt][0] = 0.f; c[nt][1] = 0.f; c[nt][2] = 0.f; c[nt][3] = 0.f;
    }

    float xr[16], wr[16];

    // Prefetch chunk 0 into registers
    #pragma unroll
    for (int i = 0; i < 16; i++) {
        int m   = xm + i * 8;
        int row = m0 + m;
        float v = 0.0f;
        if (row < N) {
            v = X[(size_t)row * D + xk];
            if (MASK_IN) v *= mask[row];
        }
        xr[i] = v;
    }
    #pragma unroll
    for (int i = 0; i < 16; i++) {
        wr[i] = W[(size_t)(wk + i * 2) * D + wc];
    }

    for (int kt = 0; kt < 4; kt++) {
        // Stage current chunk regs -> smem (with tf32 round)
        #pragma unroll
        for (int i = 0; i < 16; i++) Xs[xm + i * 8][xk] = f2tf32(xr[i]);
        #pragma unroll
        for (int i = 0; i < 16; i++) Ws[wk + i * 2][wc] = f2tf32(wr[i]);
        __syncthreads();

        // Prefetch next chunk while MMAs run
        if (kt < 3) {
            const int kb = (kt + 1) * 32;
            #pragma unroll
            for (int i = 0; i < 16; i++) {
                int m   = xm + i * 8;
                int row = m0 + m;
                float v = 0.0f;
                if (row < N) {
                    v = X[(size_t)row * D + kb + xk];
                    if (MASK_IN) v *= mask[row];
                }
                xr[i] = v;
            }
            #pragma unroll
            for (int i = 0; i < 16; i++) {
                wr[i] = W[(size_t)(kb + wk + i * 2) * D + wc];
            }
        }

        #pragma unroll
        for (int kk = 0; kk < 4; kk++) {             // k-tiles of 8
            const int k0 = kk * 8;
            const int ra = warp * 16 + gid;
            uint32_t a0 = Xs[ra    ][k0 + tig    ];
            uint32_t a1 = Xs[ra + 8][k0 + tig    ];
            uint32_t a2 = Xs[ra    ][k0 + tig + 4];
            uint32_t a3 = Xs[ra + 8][k0 + tig + 4];
            #pragma unroll
            for (int nt = 0; nt < 16; nt++) {
                uint32_t b0 = Ws[k0 + tig    ][nt * 8 + gid];
                uint32_t b1 = Ws[k0 + tig + 4][nt * 8 + gid];
                asm volatile(
                    "mma.sync.aligned.m16n8k8.row.col.f32.tf32.tf32.f32 "
                    "{%0,%1,%2,%3}, {%4,%5,%6,%7}, {%8,%9}, {%0,%1,%2,%3};\n"
                    : "+f"(c[nt][0]), "+f"(c[nt][1]),
                      "+f"(c[nt][2]), "+f"(c[nt][3])
                    : "r"(a0), "r"(a1), "r"(a2), "r"(a3),
                      "r"(b0), "r"(b1));
            }
        }
        __syncthreads();
    }

    // Epilogue: mask, convert to fp16, store half2 per (row, n-tile).
    const int r0 = m0 + warp * 16 + gid;
    const int r1 = r0 + 8;
    const float mk0 = (r0 < N) ? mask[r0] : 0.f;
    const float mk1 = (r1 < N) ? mask[r1] : 0.f;
    #pragma unroll
    for (int nt = 0; nt < 16; nt++) {
        int col = nt * 8 + tig * 2;
        if (r0 < N) {
            __half2 h = __floats2half2_rn(c[nt][0] * mk0, c[nt][1] * mk0);
            *reinterpret_cast<__half2*>(&out[(size_t)r0 * D + col]) = h;
        }
        if (r1 < N) {
            __half2 h = __floats2half2_rn(c[nt][2] * mk1, c[nt][3] * mk1);
            *reinterpret_cast<__half2*>(&out[(size_t)r1 * D + col]) = h;
        }
    }
}

// ---------------------------------------------------------------------------
// Gather + weighted sum + exp_map_zero + relu (+ optional fused log_map for
// the next layer). One warp per node; lane l owns dims [4l, 4l+4) = 8 bytes
// of the fp16 msg row. Row = 128 halves = 256 B = 32 uint2 -> stride D/4.
// ---------------------------------------------------------------------------
template<bool FUSE_LOGMAP>
__global__ __launch_bounds__(256) void gather_kernel(
    const __half* __restrict__ msg, const int* __restrict__ adj,
    const float* __restrict__ wgt, const float* __restrict__ mask,
    float* __restrict__ out, int N)
{
    const int warp = (blockIdx.x * blockDim.x + threadIdx.x) >> 5;
    const int lane = threadIdx.x & 31;
    if (warp >= N) return;
    const int n = warp;

    const int   a_reg = adj[(size_t)n * KNBR + lane];
    const float w_reg = wgt[(size_t)n * KNBR + lane];

    // lane's 4 halves: 8B at row*256B + lane*8B  (D/4 = 32 uint2 per row!)
    const uint2* msg2 = reinterpret_cast<const uint2*>(msg);
    float4 acc = make_float4(0.f, 0.f, 0.f, 0.f);

    #pragma unroll
    for (int k = 0; k < KNBR; k++) {
        int   ak = __shfl_sync(0xffffffffu, a_reg, k);
        float wk = __shfl_sync(0xffffffffu, w_reg, k);
        uint2 raw = msg2[(size_t)ak * (D / 4) + lane];
        __half2 h01 = *reinterpret_cast<__half2*>(&raw.x);
        __half2 h23 = *reinterpret_cast<__half2*>(&raw.y);
        float2 f01 = __half22float2(h01);
        float2 f23 = __half22float2(h23);
        acc.x = fmaf(wk, f01.x, acc.x);
        acc.y = fmaf(wk, f01.y, acc.y);
        acc.z = fmaf(wk, f23.x, acc.z);
        acc.w = fmaf(wk, f23.y, acc.w);
    }

    const float mk = mask[n];
    acc.x *= mk; acc.y *= mk; acc.z *= mk; acc.w *= mk;

    // exp_map_zero: tanh(clip(||v||, EPS, 15)) * v / max(||v||, EPS)
    float ss = acc.x * acc.x + acc.y * acc.y + acc.z * acc.z + acc.w * acc.w;
    #pragma unroll
    for (int o = 16; o; o >>= 1) ss += __shfl_xor_sync(0xffffffffu, ss, o);
    float nn = sqrtf(ss);
    float nc = fminf(fmaxf(nn, 1e-5f), 15.0f);
    float sc = (tanhf(nc) / fmaxf(nn, 1e-5f)) * mk;

    float4 x;
    x.x = fmaxf(acc.x * sc, 0.0f) * mk;
    x.y = fmaxf(acc.y * sc, 0.0f) * mk;
    x.z = fmaxf(acc.z * sc, 0.0f) * mk;
    x.w = fmaxf(acc.w * sc, 0.0f) * mk;

    if (FUSE_LOGMAP) {
        // next layer prologue: t = log_map_zero(x) * mask
        float s2 = x.x * x.x + x.y * x.y + x.z * x.z + x.w * x.w;
        #pragma unroll
        for (int o = 16; o; o >>= 1) s2 += __shfl_xor_sync(0xffffffffu, s2, o);
        float n2  = sqrtf(s2);
        float n2c = fminf(fmaxf(n2, 1e-5f), 1.0f - 1e-5f);
        float sl  = (atanhf(n2c) / fmaxf(n2, 1e-5f)) * mk;
        x.x *= sl; x.y *= sl; x.z *= sl; x.w *= sl;
    }

    reinterpret_cast<float4*>(out)[(size_t)n * (D / 4) + lane] = x;
}

// ---------------------------------------------------------------------------
// Launch: 2 layers x (tf32 GEMM -> fp16 msg, gather).
// ---------------------------------------------------------------------------
extern "C" void kernel_launch(void* const* d_in, const int* in_sizes, int n_in,
                              void* d_out, int out_size)
{
    const float* node_repr = (const float*)d_in[0];   // [N, D]
    const int*   adj_mat   = (const int*)  d_in[1];   // [N, K]
    const float* weight    = (const float*)d_in[2];   // [N, K]
    const float* mask      = (const float*)d_in[3];   // [N, 1]
    const float* msg_w     = (const float*)d_in[4];   // [2, D, D]
    float*       out       = (float*)d_out;           // [N, D]

    const int N = in_sizes[0] / D;

    __half* msg_buf;
    float*  x_buf;
    cudaGetSymbolAddress((void**)&msg_buf, g_msg);
    cudaGetSymbolAddress((void**)&x_buf,   g_x);

    dim3 gemm_grid((N + 127) / 128);
    int  gather_blocks = (N * 32 + 255) / 256;        // 1 warp per node

    // Layer 0
    gemm_tf32_kernel<true><<<gemm_grid, 256>>>(node_repr, msg_w, mask, msg_buf, N);
    gather_kernel<true><<<gather_blocks, 256>>>(msg_buf, adj_mat, weight, mask, x_buf, N);

    // Layer 1
    gemm_tf32_kernel<false><<<gemm_grid, 256>>>(x_buf, msg_w + D * D, mask, msg_buf, N);
    gather_kernel<false><<<gather_blocks, 256>>>(msg_buf, adj_mat, weight, mask, out, N);
}